// round 2
// baseline (speedup 1.0000x reference)
#include <cuda_runtime.h>
#include <math.h>
#include <stdint.h>

#define BATCH 8
#define NPTS  4096
#define DIM   64
#define TILE  64
#define NT    (NPTS / TILE)          // 64 tiles per dim
#define NTRI  (NT * (NT + 1) / 2)    // 2080 upper-tri tiles per batch
#define TPB   256
#define SROW  68                     // padded smem row stride (floats), 68*4 % 16 == 0

// Per-tile partial sums (sum of weighted exp over the tile), deterministic slots.
__device__ double g_partials[BATCH * NTRI];

__global__ __launch_bounds__(TPB) void nohub_tile_kernel(const float* __restrict__ emb) {
    const int bx = blockIdx.x;
    const int b  = bx / NTRI;
    int t = bx - b * NTRI;

    // Decode triangular index t -> (tn, tm) with tn <= tm, t = tm*(tm+1)/2 + tn
    int tm = (int)((__fsqrt_rn(8.0f * (float)t + 1.0f) - 1.0f) * 0.5f);
    while ((tm + 1) * (tm + 2) / 2 <= t) ++tm;
    while (tm * (tm + 1) / 2 > t) --tm;
    const int tn = t - tm * (tm + 1) / 2;

    __shared__ float As[DIM][SROW];   // As[k][n]  (transposed)
    __shared__ float Bs[DIM][SROW];   // Bs[k][m]
    __shared__ double wred[TPB / 32];

    const float* __restrict__ Ab = emb + ((size_t)b * NPTS + (size_t)tn * TILE) * DIM;
    const float* __restrict__ Bb = emb + ((size_t)b * NPTS + (size_t)tm * TILE) * DIM;

    const int tid = threadIdx.x;

    // Load + transpose: i -> row r = i&63, k-group c4 = i>>6.
    // Warp covers 32 consecutive r at fixed c4 -> conflict-free STS (n varies fastest).
    #pragma unroll
    for (int it = 0; it < 4; ++it) {
        int i  = tid + it * TPB;
        int r  = i & 63;
        int c4 = i >> 6;
        float4 va = *(const float4*)(Ab + r * DIM + c4 * 4);
        As[c4 * 4 + 0][r] = va.x;
        As[c4 * 4 + 1][r] = va.y;
        As[c4 * 4 + 2][r] = va.z;
        As[c4 * 4 + 3][r] = va.w;
        float4 vb = *(const float4*)(Bb + r * DIM + c4 * 4);
        Bs[c4 * 4 + 0][r] = vb.x;
        Bs[c4 * 4 + 1][r] = vb.y;
        Bs[c4 * 4 + 2][r] = vb.z;
        Bs[c4 * 4 + 3][r] = vb.w;
    }
    __syncthreads();

    const int tx = tid & 15;   // n sub-tile
    const int ty = tid >> 4;   // m sub-tile

    float acc[4][4];
    #pragma unroll
    for (int i = 0; i < 4; ++i)
        #pragma unroll
        for (int j = 0; j < 4; ++j) acc[i][j] = 0.0f;

    #pragma unroll 16
    for (int k = 0; k < DIM; ++k) {
        float4 a  = *(const float4*)&As[k][tx * 4];
        float4 bv = *(const float4*)&Bs[k][ty * 4];
        float ar[4] = {a.x, a.y, a.z, a.w};
        float br[4] = {bv.x, bv.y, bv.z, bv.w};
        #pragma unroll
        for (int i = 0; i < 4; ++i)
            #pragma unroll
            for (int j = 0; j < 4; ++j)
                acc[i][j] = fmaf(ar[i], br[j], acc[i][j]);
    }

    // exp(0.5 * dot) = 2^(dot * 0.5*log2(e)); MUFU.EX2 keeps this off the FMA pipe.
    const float C = 0.72134752044448170368f;  // 0.5 * log2(e)
    float s = 0.0f;
    #pragma unroll
    for (int i = 0; i < 4; ++i)
        #pragma unroll
        for (int j = 0; j < 4; ++j) {
            float e;
            asm("ex2.approx.f32 %0, %1;" : "=f"(e) : "f"(acc[i][j] * C));
            s += e;
        }

    // Deterministic block reduction in double.
    double ds = (double)s;
    #pragma unroll
    for (int o = 16; o > 0; o >>= 1)
        ds += __shfl_down_sync(0xffffffffu, ds, o);
    if ((tid & 31) == 0) wred[tid >> 5] = ds;
    __syncthreads();
    if (tid < 32) {
        double v = (tid < TPB / 32) ? wred[tid] : 0.0;
        #pragma unroll
        for (int o = 4; o > 0; o >>= 1)
            v += __shfl_down_sync(0xffffffffu, v, o);
        if (tid == 0) {
            double w = (tn == tm) ? 1.0 : 2.0;  // off-diag tiles counted twice (symmetry)
            g_partials[bx] = v * w;
        }
    }
}

__global__ __launch_bounds__(TPB) void nohub_finalize_kernel(float* __restrict__ out) {
    __shared__ double red[TPB];
    const int tid = threadIdx.x;
    double loss = 0.0;
    for (int b = 0; b < BATCH; ++b) {
        double s = 0.0;
        for (int i = tid; i < NTRI; i += TPB)
            s += g_partials[b * NTRI + i];
        red[tid] = s;
        __syncthreads();
        for (int o = TPB / 2; o > 0; o >>= 1) {
            if (tid < o) red[tid] += red[tid + o];
            __syncthreads();
        }
        if (tid == 0) loss += log(red[0]);
        __syncthreads();
    }
    if (tid == 0) *out = (float)(loss / (double)BATCH);
}

extern "C" void kernel_launch(void* const* d_in, const int* in_sizes, int n_in,
                              void* d_out, int out_size) {
    (void)in_sizes; (void)n_in; (void)out_size;
    const float* emb = (const float*)d_in[0];
    float* out = (float*)d_out;
    nohub_tile_kernel<<<BATCH * NTRI, TPB>>>(emb);
    nohub_finalize_kernel<<<1, TPB>>>(out);
}

// round 4
// speedup vs baseline: 2.8806x; 2.8806x over previous
#include <cuda_runtime.h>
#include <cuda_bf16.h>
#include <math.h>
#include <stdint.h>

#define BATCH 8
#define NPTS  4096
#define DIM   64
#define TILE  128
#define NT    (NPTS / TILE)            // 32
#define NTRI  (NT * (NT + 1) / 2)      // 528
#define TOTAL (BATCH * NTRI)           // 4224
#define GRID  148
#define TPB   256

// smem sub-tile: 128 rows x 72 bf16 (144 B stride) -> conflict-free ldmatrix
#define SROWB   144
#define SUBTILE (128 * SROWB)          // 18432 B
#define BUFSZ   (4 * SUBTILE)          // Ah, Al, Bh, Bl
#define SMEM_BYTES (2 * BUFSZ)         // 147456, double buffered

__device__ __align__(16) __nv_bfloat16 g_hi[BATCH * NPTS * DIM];
__device__ __align__(16) __nv_bfloat16 g_lo[BATCH * NPTS * DIM];
__device__ double g_partials[TOTAL];

__device__ __forceinline__ uint32_t smem_u32(const void* p) {
    uint32_t a;
    asm("{ .reg .u64 t; cvta.to.shared.u64 t, %1; cvt.u32.u64 %0, t; }" : "=r"(a) : "l"(p));
    return a;
}
__device__ __forceinline__ void ldsm4(uint32_t* r, uint32_t addr) {
    asm volatile("ldmatrix.sync.aligned.m8n8.x4.shared.b16 {%0,%1,%2,%3}, [%4];"
                 : "=r"(r[0]), "=r"(r[1]), "=r"(r[2]), "=r"(r[3]) : "r"(addr));
}
__device__ __forceinline__ void mma16816(float* d, const uint32_t* a, const uint32_t* b) {
    asm volatile(
        "mma.sync.aligned.m16n8k16.row.col.f32.bf16.bf16.f32 "
        "{%0,%1,%2,%3}, {%4,%5,%6,%7}, {%8,%9}, {%0,%1,%2,%3};"
        : "+f"(d[0]), "+f"(d[1]), "+f"(d[2]), "+f"(d[3])
        : "r"(a[0]), "r"(a[1]), "r"(a[2]), "r"(a[3]), "r"(b[0]), "r"(b[1]));
}
__device__ __forceinline__ void cp16(uint32_t dst, const void* src) {
    asm volatile("cp.async.ca.shared.global [%0], [%1], 16;" :: "r"(dst), "l"(src));
}

// ---------------- 1) split f32 -> hi/lo bf16 ----------------
__global__ __launch_bounds__(256) void split_kernel(const float* __restrict__ emb) {
    int i = (blockIdx.x * 256 + threadIdx.x) * 4;
    float4 v = *(const float4*)(emb + i);
    __nv_bfloat16 h[4], l[4];
    float x[4] = {v.x, v.y, v.z, v.w};
    #pragma unroll
    for (int j = 0; j < 4; ++j) {
        h[j] = __float2bfloat16(x[j]);
        l[j] = __float2bfloat16(x[j] - __bfloat162float(h[j]));
    }
    *(uint2*)&g_hi[i] = *(uint2*)h;
    *(uint2*)&g_lo[i] = *(uint2*)l;
}

// ---------------- 2) persistent HMMA tile kernel ----------------
__device__ __forceinline__ void load_tile(uint32_t sbase, int buf, int b, int tn, int tm,
                                          int tid) {
    const size_t arow = ((size_t)b * NPTS + (size_t)tn * TILE) * DIM;
    const size_t brow = ((size_t)b * NPTS + (size_t)tm * TILE) * DIM;
    const __nv_bfloat16* srcs[4] = {g_hi + arow, g_lo + arow, g_hi + brow, g_lo + brow};
    const uint32_t base = sbase + buf * BUFSZ;
    #pragma unroll
    for (int h = 0; h < 4; ++h) {
        const __nv_bfloat16* src = srcs[h];
        const uint32_t dst = base + h * SUBTILE;
        #pragma unroll
        for (int it = 0; it < 4; ++it) {
            int q = tid + it * TPB;        // 16B chunk id, 1024 per sub-tile
            int r = q >> 3, c = q & 7;
            cp16(dst + r * SROWB + c * 16, src + r * DIM + c * 8);
        }
    }
    asm volatile("cp.async.commit_group;" ::: "memory");
}

__global__ __launch_bounds__(TPB) void tile_kernel() {
    extern __shared__ __align__(128) char smem[];
    __shared__ double redbuf[8];
    const uint32_t sbase = smem_u32(smem);
    const int tid = threadIdx.x;
    const int wid = tid >> 5;
    const int lid = tid & 31;
    const int wm = wid & 1;            // 2 warps along M (64 rows each)
    const int wn = wid >> 1;           // 4 warps along N (32 cols each)

    // Per-lane ldmatrix byte offsets (within a sub-tile), invariant across tiles.
    // A frag (m16k16): lanes 0-7 rows m0-7 k0 | 8-15 m8-15 k0 | 16-23 m0-7 k8 | 24-31 m8-15 k8
    uint32_t offA[4];
    {
        int row = ((lid >> 3) & 1) * 8 + (lid & 7);
        int kc  = (lid >> 4) * 8;
        #pragma unroll
        for (int ma = 0; ma < 4; ++ma)
            offA[ma] = (uint32_t)((wm * 64 + ma * 16 + row) * SROWB + kc * 2);
    }
    // B frag pair (2 n-atoms): 0-7 n0-7 k0 | 8-15 n0-7 k8 | 16-23 n8-15 k0 | 24-31 n8-15 k8
    uint32_t offB[2];
    {
        int row = (lid >> 4) * 8 + (lid & 7);
        int kc  = ((lid >> 3) & 1) * 8;
        #pragma unroll
        for (int np = 0; np < 2; ++np)
            offB[np] = (uint32_t)((wn * 32 + np * 16 + row) * SROWB + kc * 2);
    }

    const float C = 0.72134752044448170368f;  // 0.5 * log2(e)

    // Decode first tile
    int t = blockIdx.x;
    int b, tn, tm;
    {
        b = t / NTRI;
        int tt = t - b * NTRI;
        tm = (int)((__fsqrt_rn(8.0f * (float)tt + 1.0f) - 1.0f) * 0.5f);
        while ((tm + 1) * (tm + 2) / 2 <= tt) ++tm;
        while (tm * (tm + 1) / 2 > tt) --tm;
        tn = tt - tm * (tm + 1) / 2;
    }
    load_tile(sbase, 0, b, tn, tm, tid);

    int buf = 0;
    for (; t < TOTAL; ) {
        const int cb = b, ctn = tn, ctm = tm, ct = t;
        const int tnext = t + GRID;
        const bool has_next = (tnext < TOTAL);
        if (has_next) {
            b = tnext / NTRI;
            int tt = tnext - b * NTRI;
            tm = (int)((__fsqrt_rn(8.0f * (float)tt + 1.0f) - 1.0f) * 0.5f);
            while ((tm + 1) * (tm + 2) / 2 <= tt) ++tm;
            while (tm * (tm + 1) / 2 > tt) --tm;
            tn = tt - tm * (tm + 1) / 2;
            load_tile(sbase, buf ^ 1, b, tn, tm, tid);
            asm volatile("cp.async.wait_group 1;" ::: "memory");
        } else {
            asm volatile("cp.async.wait_group 0;" ::: "memory");
        }
        __syncthreads();

        const uint32_t base = sbase + buf * BUFSZ;
        const uint32_t bAh = base;
        const uint32_t bAl = base + SUBTILE;
        const uint32_t bBh = base + 2 * SUBTILE;
        const uint32_t bBl = base + 3 * SUBTILE;

        float acc[4][4][4];
        #pragma unroll
        for (int i = 0; i < 4; ++i)
            #pragma unroll
            for (int j = 0; j < 4; ++j)
                #pragma unroll
                for (int e = 0; e < 4; ++e) acc[i][j][e] = 0.0f;

        #pragma unroll
        for (int ks = 0; ks < 4; ++ks) {
            const uint32_t ko = ks * 32;   // 16 bf16 = 32 B along k
            uint32_t Ah[4][4], Al[4][4], Bh[2][4], Bl[2][4];
            #pragma unroll
            for (int ma = 0; ma < 4; ++ma) {
                ldsm4(Ah[ma], bAh + offA[ma] + ko);
                ldsm4(Al[ma], bAl + offA[ma] + ko);
            }
            #pragma unroll
            for (int np = 0; np < 2; ++np) {
                ldsm4(Bh[np], bBh + offB[np] + ko);
                ldsm4(Bl[np], bBl + offB[np] + ko);
            }
            #pragma unroll
            for (int ma = 0; ma < 4; ++ma)
                #pragma unroll
                for (int nb = 0; nb < 4; ++nb) {
                    const uint32_t* bh = &Bh[nb >> 1][(nb & 1) * 2];
                    const uint32_t* bl = &Bl[nb >> 1][(nb & 1) * 2];
                    mma16816(acc[ma][nb], Ah[ma], bh);
                    mma16816(acc[ma][nb], Ah[ma], bl);
                    mma16816(acc[ma][nb], Al[ma], bh);
                }
        }

        // Epilogue: sum exp(0.5 * logit) over all 64 accumulators.
        float s[4] = {0.f, 0.f, 0.f, 0.f};
        #pragma unroll
        for (int ma = 0; ma < 4; ++ma)
            #pragma unroll
            for (int nb = 0; nb < 4; ++nb)
                #pragma unroll
                for (int e = 0; e < 4; ++e) {
                    float ex;
                    asm("ex2.approx.f32 %0, %1;" : "=f"(ex) : "f"(acc[ma][nb][e] * C));
                    s[e] += ex;
                }
        double dsum = (double)((s[0] + s[1]) + (s[2] + s[3]));
        #pragma unroll
        for (int o = 16; o > 0; o >>= 1)
            dsum += __shfl_down_sync(0xffffffffu, dsum, o);
        if (lid == 0) redbuf[wid] = dsum;
        __syncthreads();
        if (tid == 0) {
            double v = ((redbuf[0] + redbuf[1]) + (redbuf[2] + redbuf[3])) +
                       ((redbuf[4] + redbuf[5]) + (redbuf[6] + redbuf[7]));
            g_partials[ct] = (ctn == ctm) ? v : 2.0 * v;
        }
        __syncthreads();   // epilogue fully done before this buf is reloaded

        buf ^= 1;
        t = tnext;
    }
}

// ---------------- 3) finalize: warp-per-batch logsumexp mean ----------------
__global__ __launch_bounds__(256) void fin_kernel(float* __restrict__ out) {
    const int tid = threadIdx.x;
    const int w = tid >> 5, lid = tid & 31;
    __shared__ double logs[8];
    double s = 0.0;
    for (int i = lid; i < NTRI; i += 32)
        s += g_partials[w * NTRI + i];
    #pragma unroll
    for (int o = 16; o > 0; o >>= 1)
        s += __shfl_down_sync(0xffffffffu, s, o);
    if (lid == 0) logs[w] = log(s);
    __syncthreads();
    if (tid == 0) {
        double L = 0.0;
        #pragma unroll
        for (int i = 0; i < 8; ++i) L += logs[i];
        *out = (float)(L / 8.0);
    }
}

extern "C" void kernel_launch(void* const* d_in, const int* in_sizes, int n_in,
                              void* d_out, int out_size) {
    (void)in_sizes; (void)n_in; (void)out_size;
    const float* emb = (const float*)d_in[0];
    float* out = (float*)d_out;
    cudaFuncSetAttribute(tile_kernel, cudaFuncAttributeMaxDynamicSharedMemorySize, SMEM_BYTES);
    split_kernel<<<BATCH * NPTS * DIM / (256 * 4), 256>>>(emb);
    tile_kernel<<<GRID, TPB, SMEM_BYTES>>>();
    fin_kernel<<<1, 256>>>(out);
}

// round 6
// speedup vs baseline: 5.5573x; 1.9293x over previous
#include <cuda_runtime.h>
#include <cuda_fp16.h>
#include <math.h>
#include <stdint.h>

#define BATCH 8
#define NPTS  4096
#define DIM   64
#define TILE  128
#define NT    (NPTS / TILE)            // 32
#define NTRI  (NT * (NT + 1) / 2)      // 528
#define TOTAL (BATCH * NTRI)           // 4224
#define GRID  296
#define TPB   256

// smem sub-tile: 128 rows x 72 fp16 (144 B stride) -> conflict-free ldmatrix
#define SROWB   144
#define SUBTILE (128 * SROWB)          // 18432 B
#define BUFSZ   (2 * SUBTILE)          // A, B
#define SMEM_BYTES (2 * BUFSZ)         // 73728, double buffered

__device__ __align__(16) __half g_a[BATCH * NPTS * DIM];  // scaled by 0.5*log2(e)
__device__ __align__(16) __half g_b[BATCH * NPTS * DIM];
__device__ double g_partials[TOTAL];

__device__ __forceinline__ uint32_t smem_u32(const void* p) {
    uint32_t a;
    asm("{ .reg .u64 t; cvta.to.shared.u64 t, %1; cvt.u32.u64 %0, t; }" : "=r"(a) : "l"(p));
    return a;
}
__device__ __forceinline__ void ldsm4(uint32_t* r, uint32_t addr) {
    asm volatile("ldmatrix.sync.aligned.m8n8.x4.shared.b16 {%0,%1,%2,%3}, [%4];"
                 : "=r"(r[0]), "=r"(r[1]), "=r"(r[2]), "=r"(r[3]) : "r"(addr));
}
__device__ __forceinline__ void mma16816(float* d, const uint32_t* a, const uint32_t* b) {
    asm volatile(
        "mma.sync.aligned.m16n8k16.row.col.f32.f16.f16.f32 "
        "{%0,%1,%2,%3}, {%4,%5,%6,%7}, {%8,%9}, {%0,%1,%2,%3};"
        : "+f"(d[0]), "+f"(d[1]), "+f"(d[2]), "+f"(d[3])
        : "r"(a[0]), "r"(a[1]), "r"(a[2]), "r"(a[3]), "r"(b[0]), "r"(b[1]));
}
__device__ __forceinline__ void cp16(uint32_t dst, const void* src) {
    asm volatile("cp.async.ca.shared.global [%0], [%1], 16;" :: "r"(dst), "l"(src));
}

// ---------------- 1) convert f32 -> fp16 (A pre-scaled by 0.5*log2e) ----------------
__global__ __launch_bounds__(256) void split_kernel(const float* __restrict__ emb) {
    const float C = 0.72134752044448170368f;  // 0.5 * log2(e)
    int i = (blockIdx.x * 256 + threadIdx.x) * 4;
    float4 v = *(const float4*)(emb + i);
    float x[4] = {v.x, v.y, v.z, v.w};
    __half a[4], b[4];
    #pragma unroll
    for (int j = 0; j < 4; ++j) {
        a[j] = __float2half(x[j] * C);
        b[j] = __float2half(x[j]);
    }
    *(uint2*)&g_a[i] = *(uint2*)a;
    *(uint2*)&g_b[i] = *(uint2*)b;
}

// ---------------- 2) persistent HMMA tile kernel ----------------
__device__ __forceinline__ void load_tile(uint32_t sbase, int buf, int b, int tn, int tm,
                                          int tid) {
    const size_t arow = ((size_t)b * NPTS + (size_t)tn * TILE) * DIM;
    const size_t brow = ((size_t)b * NPTS + (size_t)tm * TILE) * DIM;
    const __half* srcs[2] = {g_a + arow, g_b + brow};
    const uint32_t base = sbase + buf * BUFSZ;
    #pragma unroll
    for (int h = 0; h < 2; ++h) {
        const __half* src = srcs[h];
        const uint32_t dst = base + h * SUBTILE;
        #pragma unroll
        for (int it = 0; it < 4; ++it) {
            int q = tid + it * TPB;        // 16B chunk id, 1024 per sub-tile
            int r = q >> 3, c = q & 7;
            cp16(dst + r * SROWB + c * 16, src + r * DIM + c * 8);
        }
    }
    asm volatile("cp.async.commit_group;" ::: "memory");
}

__global__ __launch_bounds__(TPB, 2) void tile_kernel() {
    extern __shared__ __align__(128) char smem[];
    __shared__ double redbuf[8];
    const uint32_t sbase = smem_u32(smem);
    const int tid = threadIdx.x;
    const int wid = tid >> 5;
    const int lid = tid & 31;
    const int wm = wid & 1;            // 2 warps along M (64 rows each)
    const int wn = wid >> 1;           // 4 warps along N (32 cols each)

    // Per-lane ldmatrix byte offsets (within a sub-tile), invariant across tiles.
    uint32_t offA[4];
    {
        int row = ((lid >> 3) & 1) * 8 + (lid & 7);
        int kc  = (lid >> 4) * 8;
        #pragma unroll
        for (int ma = 0; ma < 4; ++ma)
            offA[ma] = (uint32_t)((wm * 64 + ma * 16 + row) * SROWB + kc * 2);
    }
    uint32_t offB[2];
    {
        int row = (lid >> 4) * 8 + (lid & 7);
        int kc  = ((lid >> 3) & 1) * 8;
        #pragma unroll
        for (int np = 0; np < 2; ++np)
            offB[np] = (uint32_t)((wn * 32 + np * 16 + row) * SROWB + kc * 2);
    }

    // Decode first tile
    int t = blockIdx.x;
    int b, tn, tm;
    {
        b = t / NTRI;
        int tt = t - b * NTRI;
        tm = (int)((__fsqrt_rn(8.0f * (float)tt + 1.0f) - 1.0f) * 0.5f);
        while ((tm + 1) * (tm + 2) / 2 <= tt) ++tm;
        while (tm * (tm + 1) / 2 > tt) --tm;
        tn = tt - tm * (tm + 1) / 2;
    }
    if (t < TOTAL) load_tile(sbase, 0, b, tn, tm, tid);

    int buf = 0;
    for (; t < TOTAL; ) {
        const int ctn = tn, ctm = tm, ct = t;
        const int tnext = t + GRID;
        const bool has_next = (tnext < TOTAL);
        if (has_next) {
            b = tnext / NTRI;
            int tt = tnext - b * NTRI;
            tm = (int)((__fsqrt_rn(8.0f * (float)tt + 1.0f) - 1.0f) * 0.5f);
            while ((tm + 1) * (tm + 2) / 2 <= tt) ++tm;
            while (tm * (tm + 1) / 2 > tt) --tm;
            tn = tt - tm * (tm + 1) / 2;
            load_tile(sbase, buf ^ 1, b, tn, tm, tid);
            asm volatile("cp.async.wait_group 1;" ::: "memory");
        } else {
            asm volatile("cp.async.wait_group 0;" ::: "memory");
        }
        __syncthreads();

        const uint32_t bA = sbase + buf * BUFSZ;
        const uint32_t bB = bA + SUBTILE;

        float acc[4][4][4];
        #pragma unroll
        for (int i = 0; i < 4; ++i)
            #pragma unroll
            for (int j = 0; j < 4; ++j)
                #pragma unroll
                for (int e = 0; e < 4; ++e) acc[i][j][e] = 0.0f;

        #pragma unroll
        for (int ks = 0; ks < 4; ++ks) {
            const uint32_t ko = ks * 32;   // 16 fp16 = 32 B along k
            uint32_t A[4][4], B[2][4];
            #pragma unroll
            for (int ma = 0; ma < 4; ++ma) ldsm4(A[ma], bA + offA[ma] + ko);
            #pragma unroll
            for (int np = 0; np < 2; ++np) ldsm4(B[np], bB + offB[np] + ko);
            #pragma unroll
            for (int ma = 0; ma < 4; ++ma)
                #pragma unroll
                for (int nb = 0; nb < 4; ++nb)
                    mma16816(acc[ma][nb], A[ma], &B[nb >> 1][(nb & 1) * 2]);
        }

        // Epilogue: acc already = log2(exp(0.5*logit)) argument; just ex2 + sum.
        float s[4] = {0.f, 0.f, 0.f, 0.f};
        #pragma unroll
        for (int ma = 0; ma < 4; ++ma)
            #pragma unroll
            for (int nb = 0; nb < 4; ++nb)
                #pragma unroll
                for (int e = 0; e < 4; ++e) {
                    float ex;
                    asm("ex2.approx.f32 %0, %1;" : "=f"(ex) : "f"(acc[ma][nb][e]));
                    s[e] += ex;
                }
        double dsum = (double)((s[0] + s[1]) + (s[2] + s[3]));
        #pragma unroll
        for (int o = 16; o > 0; o >>= 1)
            dsum += __shfl_down_sync(0xffffffffu, dsum, o);
        if (lid == 0) redbuf[wid] = dsum;
        __syncthreads();
        if (tid == 0) {
            double v = ((redbuf[0] + redbuf[1]) + (redbuf[2] + redbuf[3])) +
                       ((redbuf[4] + redbuf[5]) + (redbuf[6] + redbuf[7]));
            g_partials[ct] = (ctn == ctm) ? v : 2.0 * v;
        }
        __syncthreads();   // epilogue fully done before this buf is reloaded

        buf ^= 1;
        t = tnext;
    }
}

// ---------------- 3) finalize: warp-per-batch logsumexp mean ----------------
__global__ __launch_bounds__(256) void fin_kernel(float* __restrict__ out) {
    const int tid = threadIdx.x;
    const int w = tid >> 5, lid = tid & 31;
    __shared__ double logs[8];
    double s = 0.0;
    for (int i = lid; i < NTRI; i += 32)
        s += g_partials[w * NTRI + i];
    #pragma unroll
    for (int o = 16; o > 0; o >>= 1)
        s += __shfl_down_sync(0xffffffffu, s, o);
    if (lid == 0) logs[w] = log(s);
    __syncthreads();
    if (tid == 0) {
        double L = 0.0;
        #pragma unroll
        for (int i = 0; i < 8; ++i) L += logs[i];
        *out = (float)(L / 8.0);
    }
}

extern "C" void kernel_launch(void* const* d_in, const int* in_sizes, int n_in,
                              void* d_out, int out_size) {
    (void)in_sizes; (void)n_in; (void)out_size;
    const float* emb = (const float*)d_in[0];
    float* out = (float*)d_out;
    cudaFuncSetAttribute(tile_kernel, cudaFuncAttributeMaxDynamicSharedMemorySize, SMEM_BYTES);
    split_kernel<<<BATCH * NPTS * DIM / (256 * 4), 256>>>(emb);
    tile_kernel<<<GRID, TPB, SMEM_BYTES>>>();
    fin_kernel<<<1, 256>>>(out);
}